// round 11
// baseline (speedup 1.0000x reference)
#include <cuda_runtime.h>
#include <cstdint>

#define BB 4
#define NN 65536
#define QQ 400
#define CC 20
#define MM 64
#define CH 1024                  // rows per sort chunk
#define NCHUNK (NN / CH)         // 64 chunks per batch
#define NBLK (NCHUNK * BB)       // 256 sort blocks

// ---------------- device scratch (no mallocs allowed) ----------------
__device__ float g_accX[BB*MM*QQ];     // sum x per (b,m,q)
__device__ float g_accG[BB*MM*QQ];     // sum sigma-related per (b,m,q)
__device__ float g_accL[BB*QQ];        // sum log2(sigma(-x)) per (b,q)  [negative]
__device__ int   g_segmax[BB*MM];      // inst_seg
__device__ int   g_mstart[BB*MM];      // per-batch start offset of each m
__device__ int   g_hist[BB*MM*NCHUNK]; // [b][m][chunk] counts -> offsets
__device__ int   g_smaxc[BB*MM*NCHUNK];// [b][m][chunk] per-chunk seg max
__device__ unsigned short g_rank[BB*NN];   // packed (m<<10)|rank_within_chunk
__device__ unsigned short g_sorder[BB*NN]; // point indices grouped by m
__device__ int   g_done  = 0;          // sort grid-barrier state (self-resetting)
__device__ int   g_flag  = 0;
__device__ int   g_done2 = 0;

// ---------------- fast approx ops ----------------
__device__ __forceinline__ float tanha(float x){ float r; asm("tanh.approx.f32 %0, %1;" : "=f"(r) : "f"(x)); return r; }
__device__ __forceinline__ float lg2a(float x){ float r; asm("lg2.approx.f32 %0, %1;" : "=f"(r) : "f"(x)); return r; }

// ---------------- fused sort: hist(+rank) -> scan (last block) -> scatter ----
__global__ void __launch_bounds__(256) ksort(const int* __restrict__ inst,
                                             const int* __restrict__ seg) {
    const int b   = blockIdx.y;
    const int ch  = blockIdx.x;
    const int tid = threadIdx.x;

    __shared__ int h[MM];
    __shared__ int smax[MM];
    __shared__ int s_last;
    if (tid < MM) { h[tid] = 0; smax[tid] = 0; }
    __syncthreads();

    // fused zeroing of accumulators (256 blocks x 256 thr, 2 strides)
    const int gtid = (b * NCHUNK + ch) * 256 + tid;            // 0..65535
    #pragma unroll
    for (int j = gtid; j < BB*MM*QQ; j += NBLK * 256) {
        g_accX[j] = 0.f;
        g_accG[j] = 0.f;
    }
    if (gtid < BB*QQ) g_accL[gtid] = 0.f;

    // ---- phase A: histogram; atomicAdd return value = rank within (chunk,m)
    const int base = ch * CH;
    #pragma unroll
    for (int k = 0; k < CH / 256; k++) {
        int n = base + tid + k * 256;
        int m = __ldg(inst + b * NN + n);
        int s = __ldg(seg  + b * NN + n);
        int r = atomicAdd(&h[m], 1);
        atomicMax(&smax[m], s);
        g_rank[b * NN + n] = (unsigned short)((m << 10) | r);
    }
    __syncthreads();
    if (tid < MM) {
        g_hist [(b * MM + tid) * NCHUNK + ch] = h[tid];
        g_smaxc[(b * MM + tid) * NCHUNK + ch] = smax[tid];
    }

    // ---- grid barrier: last-arriving block performs the scan
    __threadfence();
    __syncthreads();
    if (tid == 0) s_last = (atomicAdd(&g_done, 1) == NBLK - 1) ? 1 : 0;
    __syncthreads();

    if (s_last) {
        // exclusive scan of g_hist per batch (4 x 4096 entries; 64 thr/batch)
        const int per   = (BB * MM * NCHUNK) / 256;   // 64
        const int sbase = tid * per;
        const int batch = tid >> 6;                   // 64 threads per batch
        int s = 0;
        #pragma unroll 8
        for (int k = 0; k < per; k++) s += g_hist[sbase + k];
        __shared__ int sh[256];
        sh[tid] = s; __syncthreads();
        int pre = 0;
        for (int j = batch * 64; j < tid; j++) pre += sh[j];
        int run = pre;
        for (int k = 0; k < per; k++) {
            int j = sbase + k;
            int c = g_hist[j];
            g_hist[j] = run;
            if ((j & (NCHUNK - 1)) == 0)
                g_mstart[j / NCHUNK] = run;           // j/NCHUNK == b*MM+m
            run += c;
        }
        // segmax reduction: thread = (b,m)
        {
            const int bm = tid;                       // 0..255 == BB*MM
            const int* sc = g_smaxc + bm * NCHUNK;
            int mx = 0;
            #pragma unroll 8
            for (int c = 0; c < NCHUNK; c++) mx = max(mx, sc[c]);
            g_segmax[bm] = mx;
        }
        __threadfence();
        __syncthreads();
        if (tid == 0) atomicExch(&g_flag, 1);
    } else {
        if (tid == 0) {
            while (atomicAdd(&g_flag, 0) == 0) __nanosleep(64);
        }
        __syncthreads();
        __threadfence();
    }

    // ---- phase C: atomic-free scatter using recorded ranks
    __shared__ int off[MM];
    if (tid < MM) off[tid] = g_hist[(b * MM + tid) * NCHUNK + ch];
    __syncthreads();

    unsigned short* so = g_sorder + b * NN;
    #pragma unroll
    for (int k = 0; k < CH / 256; k++) {
        int n = base + tid + k * 256;
        unsigned pr = g_rank[b * NN + n];
        int m = pr >> 10;
        int r = pr & 1023;
        so[off[m] + r] = (unsigned short)n;
    }

    // ---- self-reset of barrier state for the next graph replay
    __threadfence();
    __syncthreads();
    if (tid == 0) {
        if (atomicAdd(&g_done2, 1) == NBLK - 1) {
            atomicExch(&g_done, 0);
            atomicExch(&g_flag, 0);
            atomicExch(&g_done2, 0);
        }
    }
}

// ---------------- main accumulation kernel (frozen R6 shape) ----------------
// th = tanh(x/2): sigma(x)-0.5 = th/2; sigma(-x) = 0.5 - 0.5*th
// softplus(x) = -ln(sigma(-x))  -> batched product of sigma(-x) + one lg2
#define ELEM_BODY(VX, SX, SG, PP) {              \
    float x_  = (VX);                            \
    float th_ = tanha(0.5f * x_);                \
    (SG) += 0.5f * th_;                          \
    (SX) += x_;                                  \
    (PP) *= fmaf(-0.5f, th_, 0.5f); }

__global__ void __launch_bounds__(128, 7) kmain(const float* __restrict__ mask) {
    const int b    = blockIdx.z;
    const int lane = threadIdx.x & 31;
    const int w    = threadIdx.x >> 5;
    const int wc   = blockIdx.x * 4 + w;            // 0..147
    const int RPW  = (NN + 147) / 148;              // 443 rows per warp
    int i  = wc * RPW;
    const int r1 = min(i + RPW, NN);

    const int qb = blockIdx.y * 64;
    const int q0 = qb + 2 * lane;
    const bool valid = (q0 < QQ);
    const int qc = valid ? q0 : qb;                 // clamp into a touched sector

    // mstart table in warp registers
    const int* ms = g_mstart + b * MM;
    const int ms0 = ms[lane];
    const int ms1 = ms[lane + 32];

    unsigned bal0 = __ballot_sync(0xffffffffu, ms0 <= i);
    unsigned bal1 = __ballot_sync(0xffffffffu, ms1 <= i);
    int m = __popc(bal0) + __popc(bal1) - 1;        // last m with start <= i

    auto seg_end = [&](int mm) -> int {
        int nm = mm + 1;
        int lo = __shfl_sync(0xffffffffu, ms0, nm & 31);
        int hi = __shfl_sync(0xffffffffu, ms1, nm & 31);
        return (nm >= MM) ? NN : ((nm < 32) ? lo : hi);
    };

    const unsigned short* __restrict__ so = g_sorder + b * NN;
    const float* __restrict__ xb = mask + (size_t)b * NN * QQ + qc;

    float L0 = 0.f, L1 = 0.f;

    while (i < r1) {
        while (seg_end(m) <= i) ++m;
        const int e   = min(r1, seg_end(m));
        const int s0i = i;
        float sx0 = 0.f, sx1 = 0.f, sg0 = 0.f, sg1 = 0.f;
        float p0 = 1.f, p1 = 1.f;

        // unroll-8: front-batched indices, 8 streaming gathers in flight
        for (; i + 8 <= e; i += 8) {
            int ns[8];
            #pragma unroll
            for (int k = 0; k < 8; k++) ns[k] = so[i + k];
            float2 v[8];
            #pragma unroll
            for (int k = 0; k < 8; k++)
                v[k] = __ldcs(reinterpret_cast<const float2*>(xb + (size_t)ns[k] * QQ));
            #pragma unroll
            for (int k = 0; k < 8; k++) {
                ELEM_BODY(v[k].x, sx0, sg0, p0);
                ELEM_BODY(v[k].y, sx1, sg1, p1);
            }
            L0 += lg2a(p0); p0 = 1.f;
            L1 += lg2a(p1); p1 = 1.f;
        }
        for (; i < e; ++i) {
            int ns = so[i];
            float2 v = __ldcs(reinterpret_cast<const float2*>(xb + (size_t)ns * QQ));
            ELEM_BODY(v.x, sx0, sg0, p0);
            ELEM_BODY(v.y, sx1, sg1, p1);
        }
        L0 += lg2a(p0);
        L1 += lg2a(p1);

        // flush per-m sums (warp-uniform m; 256B coalesced atomic region)
        const int scnt = e - s0i;
        if (valid & (scnt > 0)) {
            float half = 0.5f * (float)scnt;
            float* aX = g_accX + ((b * MM + m) * QQ);
            float* aG = g_accG + ((b * MM + m) * QQ);
            atomicAdd(aX + q0,     sx0);
            atomicAdd(aX + q0 + 1, sx1);
            atomicAdd(aG + q0,     sg0 + half);
            atomicAdd(aG + q0 + 1, sg1 + half);
        }
    }
    if (valid) {
        atomicAdd(g_accL + b * QQ + q0,     L0);
        atomicAdd(g_accL + b * QQ + q0 + 1, L1);
    }
}

// ---------------- finalize: softmax + combine ----------------
__global__ void kfin(const float* __restrict__ cls, float* __restrict__ out) {
    const int q = blockIdx.x;
    const int b = blockIdx.y;
    const int m = threadIdx.x;   // 64 threads

    __shared__ float sl[CC];
    __shared__ float redG[MM];

    if (m < CC) sl[m] = cls[((size_t)b * QQ + q) * CC + m];

    const float X = g_accX[(b * MM + m) * QQ + q];
    const float G = g_accG[(b * MM + m) * QQ + q];
    redG[m] = G;
    __syncthreads();

    float mx = -1e30f;
    #pragma unroll
    for (int c = 0; c < CC; c++) mx = fmaxf(mx, sl[c]);
    float sum = 0.f;
    #pragma unroll
    for (int c = 0; c < CC; c++) sum += __expf(sl[c] - mx);

    float sigtot = 0.f;
    #pragma unroll
    for (int c = 0; c < MM; c++) sigtot += redG[c];

    const float Ltot = g_accL[b * QQ + q];      // sum log2(sigma(-x)) <= 0
    const float SPtot = -0.6931471805599453f * Ltot;

    const int st  = g_mstart[b * MM + m];
    const int en  = (m < MM - 1) ? g_mstart[b * MM + m + 1] : NN;
    const float cnt = (float)(en - st);

    const int segm = g_segmax[b * MM + m];
    const float prob = __expf(sl[segm] - mx) / sum;

    const float cmask  = (SPtot - X) * (1.0f / (float)NN);
    const float cclass = 1.0f - prob;
    const float cdice  = 1.0f - (2.0f * G + 1.0f) / (sigtot + cnt + 1.0f);

    out[((size_t)b * QQ + q) * MM + m] = cmask + cclass + cdice;
}

// ---------------- launcher ----------------
extern "C" void kernel_launch(void* const* d_in, const int* in_sizes, int n_in,
                              void* d_out, int out_size) {
    const float* mask = (const float*)d_in[0];   // [B,N,Q]
    const float* cls  = (const float*)d_in[1];   // [B,Q,C]
    const int*   inst = (const int*)d_in[2];     // [B,N]
    const int*   seg  = (const int*)d_in[3];     // [B,N]
    float*       out  = (float*)d_out;           // [B,Q,M]

    ksort<<<dim3(NCHUNK, BB), 256>>>(inst, seg);
    kmain<<<dim3(37, 7, BB), 128>>>(mask);
    kfin<<<dim3(QQ, BB), MM>>>(cls, out);
}

// round 12
// speedup vs baseline: 1.3625x; 1.3625x over previous
#include <cuda_runtime.h>
#include <cstdint>

#define BB 4
#define NN 65536
#define QQ 400
#define CC 20
#define MM 64
#define CH 1024                  // rows per sort chunk
#define NCHUNK (NN / CH)         // 64 chunks per batch

// ---------------- device scratch (no mallocs allowed) ----------------
__device__ float g_accX[BB*MM*QQ];     // sum x per (b,m,q)
__device__ float g_accG[BB*MM*QQ];     // sum sigma-related per (b,m,q)
__device__ float g_accL[BB*QQ];        // sum log2(sigma(-x)) per (b,q)  [negative]
__device__ int   g_segmax[BB*MM];      // inst_seg
__device__ int   g_mstart[BB*MM];      // per-batch start offset of each m
__device__ int   g_hist[BB*MM*NCHUNK]; // [b][m][chunk] counts
__device__ int   g_smaxc[BB*MM*NCHUNK];// [b][m][chunk] per-chunk seg max
__device__ unsigned short g_rank[BB*NN];   // packed (m<<10)|rank_within_chunk
__device__ unsigned short g_sorder[BB*NN]; // point indices grouped by m

// ---------------- fast approx ops ----------------
__device__ __forceinline__ float tanha(float x){ float r; asm("tanh.approx.f32 %0, %1;" : "=f"(r) : "f"(x)); return r; }
__device__ __forceinline__ float lg2a(float x){ float r; asm("lg2.approx.f32 %0, %1;" : "=f"(r) : "f"(x)); return r; }

// ---------------- pass 1: histogram + rank recording + segmax + zero accs ----
__global__ void __launch_bounds__(256) khist(const int* __restrict__ inst,
                                             const int* __restrict__ seg) {
    const int b   = blockIdx.y;
    const int ch  = blockIdx.x;
    const int tid = threadIdx.x;
    __shared__ int h[MM];
    __shared__ int smax[MM];
    if (tid < MM) { h[tid] = 0; smax[tid] = 0; }
    __syncthreads();

    // fused zeroing of accumulators (256 blocks x 256 thr, 2 strides)
    const int gtid = (b * NCHUNK + ch) * 256 + tid;            // 0..65535
    #pragma unroll
    for (int j = gtid; j < BB*MM*QQ; j += BB*NCHUNK*256) {
        g_accX[j] = 0.f;
        g_accG[j] = 0.f;
    }
    if (gtid < BB*QQ) g_accL[gtid] = 0.f;

    // histogram; atomicAdd return value = rank within (chunk, m)
    const int base = ch * CH;
    #pragma unroll
    for (int k = 0; k < CH / 256; k++) {
        int n = base + tid + k * 256;
        int m = __ldg(inst + b * NN + n);
        int s = __ldg(seg  + b * NN + n);
        int r = atomicAdd(&h[m], 1);
        atomicMax(&smax[m], s);
        g_rank[b * NN + n] = (unsigned short)((m << 10) | r);
    }
    __syncthreads();
    if (tid < MM) {
        g_hist [(b * MM + tid) * NCHUNK + ch] = h[tid];
        g_smaxc[(b * MM + tid) * NCHUNK + ch] = smax[tid];
    }
}

// ---------------- pass 2: per-block in-shared scan + atomic-free scatter -----
__global__ void __launch_bounds__(256) kscatter() {
    const int b   = blockIdx.y;
    const int ch  = blockIdx.x;
    const int tid = threadIdx.x;

    // load the full per-batch histogram (64 m x 64 ch = 4096 ints, 16 KB)
    __shared__ int sh[MM * NCHUNK];
    #pragma unroll
    for (int j = tid; j < MM * NCHUNK; j += 256)
        sh[j] = g_hist[b * MM * NCHUNK + j];
    __syncthreads();

    __shared__ int rowtot[MM];
    __shared__ int partial[MM];
    if (tid < MM) {
        const int m = tid;
        int pre = 0, tot = 0;
        #pragma unroll 8
        for (int c = 0; c < NCHUNK; c++) {
            int v = sh[m * NCHUNK + c];
            pre += (c < ch) ? v : 0;
            tot += v;
        }
        rowtot[m]  = tot;
        partial[m] = pre;
    }
    __syncthreads();

    __shared__ int off[MM];
    if (tid < MM) {
        int base = 0;                      // exclusive scan over m (64 bcast reads)
        for (int m2 = 0; m2 < tid; m2++) base += rowtot[m2];
        off[tid] = base + partial[tid];
        if (ch == 0) {
            g_mstart[b * MM + tid] = base;
            const int* sc = g_smaxc + (b * MM + tid) * NCHUNK;
            int mx = 0;
            #pragma unroll 8
            for (int c = 0; c < NCHUNK; c++) mx = max(mx, sc[c]);
            g_segmax[b * MM + tid] = mx;
        }
    }
    __syncthreads();

    // atomic-free scatter using the recorded ranks
    const int base = ch * CH;
    unsigned short* so = g_sorder + b * NN;
    #pragma unroll
    for (int k = 0; k < CH / 256; k++) {
        int n = base + tid + k * 256;
        unsigned pr = g_rank[b * NN + n];
        int m = pr >> 10;
        int r = pr & 1023;
        so[off[m] + r] = (unsigned short)n;
    }
}

// ---------------- main accumulation kernel (frozen R6 shape) ----------------
// th = tanh(x/2): sigma(x)-0.5 = th/2; sigma(-x) = 0.5 - 0.5*th
// softplus(x) = -ln(sigma(-x))  -> batched product of sigma(-x) + one lg2
#define ELEM_BODY(VX, SX, SG, PP) {              \
    float x_  = (VX);                            \
    float th_ = tanha(0.5f * x_);                \
    (SG) += 0.5f * th_;                          \
    (SX) += x_;                                  \
    (PP) *= fmaf(-0.5f, th_, 0.5f); }

__global__ void __launch_bounds__(128, 7) kmain(const float* __restrict__ mask) {
    const int b    = blockIdx.z;
    const int lane = threadIdx.x & 31;
    const int w    = threadIdx.x >> 5;
    const int wc   = blockIdx.x * 4 + w;            // 0..147
    const int RPW  = (NN + 147) / 148;              // 443 rows per warp
    int i  = wc * RPW;
    const int r1 = min(i + RPW, NN);

    const int qb = blockIdx.y * 64;
    const int q0 = qb + 2 * lane;
    const bool valid = (q0 < QQ);
    const int qc = valid ? q0 : qb;                 // clamp into a touched sector

    // mstart table in warp registers
    const int* ms = g_mstart + b * MM;
    const int ms0 = ms[lane];
    const int ms1 = ms[lane + 32];

    unsigned bal0 = __ballot_sync(0xffffffffu, ms0 <= i);
    unsigned bal1 = __ballot_sync(0xffffffffu, ms1 <= i);
    int m = __popc(bal0) + __popc(bal1) - 1;        // last m with start <= i

    auto seg_end = [&](int mm) -> int {
        int nm = mm + 1;
        int lo = __shfl_sync(0xffffffffu, ms0, nm & 31);
        int hi = __shfl_sync(0xffffffffu, ms1, nm & 31);
        return (nm >= MM) ? NN : ((nm < 32) ? lo : hi);
    };

    const unsigned short* __restrict__ so = g_sorder + b * NN;
    const float* __restrict__ xb = mask + (size_t)b * NN * QQ + qc;

    float L0 = 0.f, L1 = 0.f;

    while (i < r1) {
        while (seg_end(m) <= i) ++m;
        const int e   = min(r1, seg_end(m));
        const int s0i = i;
        float sx0 = 0.f, sx1 = 0.f, sg0 = 0.f, sg1 = 0.f;
        float p0 = 1.f, p1 = 1.f;

        // unroll-8: front-batched indices, 8 streaming gathers in flight
        for (; i + 8 <= e; i += 8) {
            int ns[8];
            #pragma unroll
            for (int k = 0; k < 8; k++) ns[k] = so[i + k];
            float2 v[8];
            #pragma unroll
            for (int k = 0; k < 8; k++)
                v[k] = __ldcs(reinterpret_cast<const float2*>(xb + (size_t)ns[k] * QQ));
            #pragma unroll
            for (int k = 0; k < 8; k++) {
                ELEM_BODY(v[k].x, sx0, sg0, p0);
                ELEM_BODY(v[k].y, sx1, sg1, p1);
            }
            L0 += lg2a(p0); p0 = 1.f;
            L1 += lg2a(p1); p1 = 1.f;
        }
        for (; i < e; ++i) {
            int ns = so[i];
            float2 v = __ldcs(reinterpret_cast<const float2*>(xb + (size_t)ns * QQ));
            ELEM_BODY(v.x, sx0, sg0, p0);
            ELEM_BODY(v.y, sx1, sg1, p1);
        }
        L0 += lg2a(p0);
        L1 += lg2a(p1);

        // flush per-m sums (warp-uniform m; 256B coalesced atomic region)
        const int scnt = e - s0i;
        if (valid & (scnt > 0)) {
            float half = 0.5f * (float)scnt;
            float* aX = g_accX + ((b * MM + m) * QQ);
            float* aG = g_accG + ((b * MM + m) * QQ);
            atomicAdd(aX + q0,     sx0);
            atomicAdd(aX + q0 + 1, sx1);
            atomicAdd(aG + q0,     sg0 + half);
            atomicAdd(aG + q0 + 1, sg1 + half);
        }
    }
    if (valid) {
        atomicAdd(g_accL + b * QQ + q0,     L0);
        atomicAdd(g_accL + b * QQ + q0 + 1, L1);
    }
}

// ---------------- finalize: softmax + combine ----------------
__global__ void kfin(const float* __restrict__ cls, float* __restrict__ out) {
    const int q = blockIdx.x;
    const int b = blockIdx.y;
    const int m = threadIdx.x;   // 64 threads

    __shared__ float sl[CC];
    __shared__ float redG[MM];

    if (m < CC) sl[m] = cls[((size_t)b * QQ + q) * CC + m];

    const float X = g_accX[(b * MM + m) * QQ + q];
    const float G = g_accG[(b * MM + m) * QQ + q];
    redG[m] = G;
    __syncthreads();

    float mx = -1e30f;
    #pragma unroll
    for (int c = 0; c < CC; c++) mx = fmaxf(mx, sl[c]);
    float sum = 0.f;
    #pragma unroll
    for (int c = 0; c < CC; c++) sum += __expf(sl[c] - mx);

    float sigtot = 0.f;
    #pragma unroll
    for (int c = 0; c < MM; c++) sigtot += redG[c];

    const float Ltot = g_accL[b * QQ + q];      // sum log2(sigma(-x)) <= 0
    const float SPtot = -0.6931471805599453f * Ltot;

    const int st  = g_mstart[b * MM + m];
    const int en  = (m < MM - 1) ? g_mstart[b * MM + m + 1] : NN;
    const float cnt = (float)(en - st);

    const int segm = g_segmax[b * MM + m];
    const float prob = __expf(sl[segm] - mx) / sum;

    const float cmask  = (SPtot - X) * (1.0f / (float)NN);
    const float cclass = 1.0f - prob;
    const float cdice  = 1.0f - (2.0f * G + 1.0f) / (sigtot + cnt + 1.0f);

    out[((size_t)b * QQ + q) * MM + m] = cmask + cclass + cdice;
}

// ---------------- launcher ----------------
extern "C" void kernel_launch(void* const* d_in, const int* in_sizes, int n_in,
                              void* d_out, int out_size) {
    const float* mask = (const float*)d_in[0];   // [B,N,Q]
    const float* cls  = (const float*)d_in[1];   // [B,Q,C]
    const int*   inst = (const int*)d_in[2];     // [B,N]
    const int*   seg  = (const int*)d_in[3];     // [B,N]
    float*       out  = (float*)d_out;           // [B,Q,M]

    khist<<<dim3(NCHUNK, BB), 256>>>(inst, seg);
    kscatter<<<dim3(NCHUNK, BB), 256>>>();
    kmain<<<dim3(37, 7, BB), 128>>>(mask);
    kfin<<<dim3(QQ, BB), MM>>>(cls, out);
}

// round 13
// speedup vs baseline: 1.3847x; 1.0162x over previous
#include <cuda_runtime.h>
#include <cstdint>

#define BB 4
#define NN 65536
#define QQ 400
#define CC 20
#define MM 64
#define CH 1024                  // rows per sort chunk
#define NCHUNK (NN / CH)         // 64 chunks per batch
#define TQ 16                    // q-tile for kfin (400 = 25*16)

// ---------------- device scratch (no mallocs allowed) ----------------
__device__ float g_accX[BB*MM*QQ];     // sum x per (b,m,q)
__device__ float g_accG[BB*MM*QQ];     // sum sigmoid per (b,m,q)
__device__ float g_accL[BB*QQ];        // sum log2(sigma(-x)) per (b,q)  [negative]
__device__ int   g_segmax[BB*MM];      // inst_seg
__device__ int   g_mstart[BB*MM];      // per-batch start offset of each m
__device__ int   g_hist[BB*MM*NCHUNK]; // [b][m][chunk] counts
__device__ int   g_smaxc[BB*MM*NCHUNK];// [b][m][chunk] per-chunk seg max
__device__ unsigned short g_rank[BB*NN];   // packed (m<<10)|rank_within_chunk
__device__ unsigned short g_sorder[BB*NN]; // point indices grouped by m

// ---------------- fast approx ops ----------------
__device__ __forceinline__ float tanha(float x){ float r; asm("tanh.approx.f32 %0, %1;" : "=f"(r) : "f"(x)); return r; }
__device__ __forceinline__ float lg2a(float x){ float r; asm("lg2.approx.f32 %0, %1;" : "=f"(r) : "f"(x)); return r; }
__device__ __forceinline__ float rcpa(float x){ float r; asm("rcp.approx.f32 %0, %1;" : "=f"(r) : "f"(x)); return r; }

// ---------------- pass 1: histogram + rank recording + segmax + zero accs ----
__global__ void __launch_bounds__(256) khist(const int* __restrict__ inst,
                                             const int* __restrict__ seg) {
    const int b   = blockIdx.y;
    const int ch  = blockIdx.x;
    const int tid = threadIdx.x;
    __shared__ int h[MM];
    __shared__ int smax[MM];
    if (tid < MM) { h[tid] = 0; smax[tid] = 0; }
    __syncthreads();

    // fused zeroing of accumulators (256 blocks x 256 thr, 2 strides)
    const int gtid = (b * NCHUNK + ch) * 256 + tid;            // 0..65535
    #pragma unroll
    for (int j = gtid; j < BB*MM*QQ; j += BB*NCHUNK*256) {
        g_accX[j] = 0.f;
        g_accG[j] = 0.f;
    }
    if (gtid < BB*QQ) g_accL[gtid] = 0.f;

    // histogram; atomicAdd return value = rank within (chunk, m)
    const int base = ch * CH;
    #pragma unroll
    for (int k = 0; k < CH / 256; k++) {
        int n = base + tid + k * 256;
        int m = __ldg(inst + b * NN + n);
        int s = __ldg(seg  + b * NN + n);
        int r = atomicAdd(&h[m], 1);
        atomicMax(&smax[m], s);
        g_rank[b * NN + n] = (unsigned short)((m << 10) | r);
    }
    __syncthreads();
    if (tid < MM) {
        g_hist [(b * MM + tid) * NCHUNK + ch] = h[tid];
        g_smaxc[(b * MM + tid) * NCHUNK + ch] = smax[tid];
    }
}

// ---------------- pass 2: per-block in-shared scan + atomic-free scatter -----
__global__ void __launch_bounds__(256) kscatter() {
    const int b   = blockIdx.y;
    const int ch  = blockIdx.x;
    const int tid = threadIdx.x;

    // load the full per-batch histogram (64 m x 64 ch = 4096 ints, 16 KB)
    __shared__ int sh[MM * NCHUNK];
    #pragma unroll
    for (int j = tid; j < MM * NCHUNK; j += 256)
        sh[j] = g_hist[b * MM * NCHUNK + j];
    __syncthreads();

    __shared__ int rowtot[MM];
    __shared__ int partial[MM];
    if (tid < MM) {
        const int m = tid;
        int pre = 0, tot = 0;
        #pragma unroll 8
        for (int c = 0; c < NCHUNK; c++) {
            int v = sh[m * NCHUNK + c];
            pre += (c < ch) ? v : 0;
            tot += v;
        }
        rowtot[m]  = tot;
        partial[m] = pre;
    }
    __syncthreads();

    __shared__ int off[MM];
    if (tid < MM) {
        int base = 0;                      // exclusive scan over m (64 bcast reads)
        for (int m2 = 0; m2 < tid; m2++) base += rowtot[m2];
        off[tid] = base + partial[tid];
        if (ch == 0) {
            g_mstart[b * MM + tid] = base;
            const int* sc = g_smaxc + (b * MM + tid) * NCHUNK;
            int mx = 0;
            #pragma unroll 8
            for (int c = 0; c < NCHUNK; c++) mx = max(mx, sc[c]);
            g_segmax[b * MM + tid] = mx;
        }
    }
    __syncthreads();

    // atomic-free scatter using the recorded ranks
    const int base = ch * CH;
    unsigned short* so = g_sorder + b * NN;
    #pragma unroll
    for (int k = 0; k < CH / 256; k++) {
        int n = base + tid + k * 256;
        unsigned pr = g_rank[b * NN + n];
        int m = pr >> 10;
        int r = pr & 1023;
        so[off[m] + r] = (unsigned short)n;
    }
}

// ---------------- main accumulation kernel (frozen R6 shape) ----------------
// th = tanh(x/2): sigma(x)-0.5 = th/2; sigma(-x) = 0.5 - 0.5*th
// softplus(x) = -ln(sigma(-x))  -> batched product of sigma(-x) + one lg2
#define ELEM_BODY(VX, SX, SG, PP) {              \
    float x_  = (VX);                            \
    float th_ = tanha(0.5f * x_);                \
    (SG) += 0.5f * th_;                          \
    (SX) += x_;                                  \
    (PP) *= fmaf(-0.5f, th_, 0.5f); }

__global__ void __launch_bounds__(128, 7) kmain(const float* __restrict__ mask) {
    const int b    = blockIdx.z;
    const int lane = threadIdx.x & 31;
    const int w    = threadIdx.x >> 5;
    const int wc   = blockIdx.x * 4 + w;            // 0..147
    const int RPW  = (NN + 147) / 148;              // 443 rows per warp
    int i  = wc * RPW;
    const int r1 = min(i + RPW, NN);

    const int qb = blockIdx.y * 64;
    const int q0 = qb + 2 * lane;
    const bool valid = (q0 < QQ);
    const int qc = valid ? q0 : qb;                 // clamp into a touched sector

    // mstart table in warp registers
    const int* ms = g_mstart + b * MM;
    const int ms0 = ms[lane];
    const int ms1 = ms[lane + 32];

    unsigned bal0 = __ballot_sync(0xffffffffu, ms0 <= i);
    unsigned bal1 = __ballot_sync(0xffffffffu, ms1 <= i);
    int m = __popc(bal0) + __popc(bal1) - 1;        // last m with start <= i

    auto seg_end = [&](int mm) -> int {
        int nm = mm + 1;
        int lo = __shfl_sync(0xffffffffu, ms0, nm & 31);
        int hi = __shfl_sync(0xffffffffu, ms1, nm & 31);
        return (nm >= MM) ? NN : ((nm < 32) ? lo : hi);
    };

    const unsigned short* __restrict__ so = g_sorder + b * NN;
    const float* __restrict__ xb = mask + (size_t)b * NN * QQ + qc;

    float L0 = 0.f, L1 = 0.f;

    while (i < r1) {
        while (seg_end(m) <= i) ++m;
        const int e   = min(r1, seg_end(m));
        const int s0i = i;
        float sx0 = 0.f, sx1 = 0.f, sg0 = 0.f, sg1 = 0.f;
        float p0 = 1.f, p1 = 1.f;

        // unroll-8: front-batched indices, 8 streaming gathers in flight
        for (; i + 8 <= e; i += 8) {
            int ns[8];
            #pragma unroll
            for (int k = 0; k < 8; k++) ns[k] = so[i + k];
            float2 v[8];
            #pragma unroll
            for (int k = 0; k < 8; k++)
                v[k] = __ldcs(reinterpret_cast<const float2*>(xb + (size_t)ns[k] * QQ));
            #pragma unroll
            for (int k = 0; k < 8; k++) {
                ELEM_BODY(v[k].x, sx0, sg0, p0);
                ELEM_BODY(v[k].y, sx1, sg1, p1);
            }
            L0 += lg2a(p0); p0 = 1.f;
            L1 += lg2a(p1); p1 = 1.f;
        }
        for (; i < e; ++i) {
            int ns = so[i];
            float2 v = __ldcs(reinterpret_cast<const float2*>(xb + (size_t)ns * QQ));
            ELEM_BODY(v.x, sx0, sg0, p0);
            ELEM_BODY(v.y, sx1, sg1, p1);
        }
        L0 += lg2a(p0);
        L1 += lg2a(p1);

        // flush per-m sums (warp-uniform m; 256B coalesced atomic region)
        const int scnt = e - s0i;
        if (valid & (scnt > 0)) {
            float half = 0.5f * (float)scnt;
            float* aX = g_accX + ((b * MM + m) * QQ);
            float* aG = g_accG + ((b * MM + m) * QQ);
            atomicAdd(aX + q0,     sx0);
            atomicAdd(aX + q0 + 1, sx1);
            atomicAdd(aG + q0,     sg0 + half);
            atomicAdd(aG + q0 + 1, sg1 + half);
        }
    }
    if (valid) {
        atomicAdd(g_accL + b * QQ + q0,     L0);
        atomicAdd(g_accL + b * QQ + q0 + 1, L1);
    }
}

// ---------------- finalize: tiled, coalesced softmax + combine --------------
__global__ void __launch_bounds__(256) kfin(const float* __restrict__ cls,
                                            float* __restrict__ out) {
    const int qt  = blockIdx.x;         // 0..24 (16 q each; 400 = 25*16)
    const int b   = blockIdx.y;
    const int tid = threadIdx.x;
    const int ql  = tid & (TQ - 1);     // q within tile
    const int mu  = tid >> 4;           // m-group 0..15
    const int qbase = qt * TQ;
    const int q = qbase + ql;

    __shared__ float tP[TQ * 65];       // partial cost [q][m]
    __shared__ float tG[TQ * 65];       // sigmoid sums [q][m]
    __shared__ float s_prob[TQ][CC];
    __shared__ float s_part[16][TQ];
    __shared__ float s_sig[TQ];
    __shared__ float s_SP[TQ];
    __shared__ int   s_seg[MM];
    __shared__ float s_cnt[MM];

    if (tid < MM) {
        s_seg[tid] = g_segmax[b * MM + tid];
        int st = g_mstart[b * MM + tid];
        int en = (tid < MM - 1) ? g_mstart[b * MM + tid + 1] : NN;
        s_cnt[tid] = (float)(en - st);
    }
    if (mu == 0) {                       // per-q softmax (16 threads)
        const float* cl = cls + ((size_t)b * QQ + q) * CC;
        float v[CC];
        float mx = -1e30f;
        #pragma unroll
        for (int c = 0; c < CC; c++) { v[c] = cl[c]; mx = fmaxf(mx, v[c]); }
        float sum = 0.f;
        #pragma unroll
        for (int c = 0; c < CC; c++) { float e = __expf(v[c] - mx); s_prob[ql][c] = e; sum += e; }
        float inv = rcpa(sum);
        #pragma unroll
        for (int c = 0; c < CC; c++) s_prob[ql][c] *= inv;
    } else if (mu == 1) {
        s_SP[ql] = -0.6931471805599453f * g_accL[b * QQ + q];
    }
    __syncthreads();

    const float invN = 1.0f / (float)NN;
    float psum = 0.f;
    #pragma unroll
    for (int k = 0; k < 4; k++) {        // m = mu + 16k covers all 64 m
        int m = mu + 16 * k;
        float X = g_accX[(b * MM + m) * QQ + q];
        float G = g_accG[(b * MM + m) * QQ + q];
        float cmask  = (s_SP[ql] - X) * invN;
        float cclass = 1.0f - s_prob[ql][s_seg[m]];
        tP[ql * 65 + m] = cmask + cclass + 1.0f;   // fold dice's leading 1
        tG[ql * 65 + m] = G;
        psum += G;
    }
    s_part[mu][ql] = psum;
    __syncthreads();
    if (mu == 0) {
        float s = 0.f;
        #pragma unroll
        for (int j = 0; j < 16; j++) s += s_part[j][ql];
        s_sig[ql] = s;
    }
    __syncthreads();

    // coalesced contiguous write: 16 q x 64 m = 1024 floats per tile
    float* ob = out + ((size_t)b * QQ + qbase) * MM;
    #pragma unroll
    for (int k = 0; k < (TQ * MM) / 256; k++) {    // 4
        int idx  = tid + 256 * k;
        int qloc = idx >> 6, m = idx & 63;
        float G  = tG[qloc * 65 + m];
        ob[idx]  = tP[qloc * 65 + m]
                 - (2.0f * G + 1.0f) * rcpa(s_sig[qloc] + s_cnt[m] + 1.0f);
    }
}

// ---------------- launcher ----------------
extern "C" void kernel_launch(void* const* d_in, const int* in_sizes, int n_in,
                              void* d_out, int out_size) {
    const float* mask = (const float*)d_in[0];   // [B,N,Q]
    const float* cls  = (const float*)d_in[1];   // [B,Q,C]
    const int*   inst = (const int*)d_in[2];     // [B,N]
    const int*   seg  = (const int*)d_in[3];     // [B,N]
    float*       out  = (float*)d_out;           // [B,Q,M]

    khist<<<dim3(NCHUNK, BB), 256>>>(inst, seg);
    kscatter<<<dim3(NCHUNK, BB), 256>>>();
    kmain<<<dim3(37, 7, BB), 128>>>(mask);
    kfin<<<dim3(QQ / TQ, BB), 256>>>(cls, out);
}